// round 1
// baseline (speedup 1.0000x reference)
#include <cuda_runtime.h>
#include <cuda_bf16.h>

// CRF NLL: B sentences, T steps, K=9 tags (START=7, STOP=8), 7 live states.
// Pipeline: perm (bucket by length) -> chunk (parallel scan operators, linear
// domain with rescaling, fused gold partials) -> combine (fold per sentence)
// -> reduce (mean).

#define NCH 32     // time chunks
#define NS  7      // live states 0..6
#define KK  9
#define MAXB 2048

__device__ float g_scratch[(size_t)NCH * 64 * MAXB]; // [(c*64 + s*8 + j)*B + b]
__device__ float g_gold[NCH * MAXB];
__device__ int   g_perm[MAXB];
__device__ float g_psent[MAXB];

// ---------------------------------------------------------------------------
// Bucket sentences by length so warp lanes in the chunk kernel have similar
// active ranges (restores the ~2x saving from variable lengths).
// Scatter order within a bucket is atomic (nondeterministic), but each
// sentence's arithmetic is independent of lane placement and the final
// reduction is in fixed original order, so the output is deterministic.
// ---------------------------------------------------------------------------
__global__ void perm_kernel(const int* __restrict__ lengths, int B, int C)
{
    __shared__ int hist[NCH];
    __shared__ int off[NCH];
    int tid = threadIdx.x;
    if (tid < NCH) hist[tid] = 0;
    __syncthreads();
    for (int b = tid; b < B; b += blockDim.x) {
        int bk = (lengths[b] - 1) / C;
        if (bk > NCH - 1) bk = NCH - 1;
        atomicAdd(&hist[bk], 1);
    }
    __syncthreads();
    if (tid == 0) {
        int acc = 0;
        for (int i = 0; i < NCH; i++) { off[i] = acc; acc += hist[i]; }
    }
    __syncthreads();
    for (int b = tid; b < B; b += blockDim.x) {
        int bk = (lengths[b] - 1) / C;
        if (bk > NCH - 1) bk = NCH - 1;
        int pos = atomicAdd(&off[bk], 1);
        g_perm[pos] = b;
    }
}

// ---------------------------------------------------------------------------
// Per-chunk scan body: evolve NCOLS columns of the linear-domain operator.
// ---------------------------------------------------------------------------
template<int NCOLS>
__device__ __forceinline__ void run_steps(
    int t, int t1,
    const float* __restrict__ fb, const int* __restrict__ tgb,
    const float* s_tr, const float (&et)[NS][NS],
    float (&v)[NCOLS][NS], float (&csc)[NCOLS], float& gold, int& prev)
{
    int rc = 0;
    for (; t < t1; ++t) {
        float f[NS];
        #pragma unroll
        for (int j = 0; j < NS; j++) f[j] = __ldg(&fb[t * KK + j]);
        float ef[NS];
        #pragma unroll
        for (int j = 0; j < NS; j++) ef[j] = __expf(f[j]);

        int tag = __ldg(&tgb[t]);
        float fe = f[0];
        #pragma unroll
        for (int j = 1; j < NS; j++) fe = (tag == j) ? f[j] : fe;
        gold += s_tr[tag * KK + prev] + fe;
        prev = tag;

        #pragma unroll
        for (int s = 0; s < NCOLS; s++) {
            float nv[NS];
            #pragma unroll
            for (int j = 0; j < NS; j++) {
                float a = et[j][0] * v[s][0];
                #pragma unroll
                for (int i = 1; i < NS; i++) a = fmaf(et[j][i], v[s][i], a);
                nv[j] = a;
            }
            #pragma unroll
            for (int j = 0; j < NS; j++) v[s][j] = nv[j] * ef[j];
        }
        if (++rc == 4) {   // rescale: growth <= ~e^10/step, 4 steps safe
            rc = 0;
            #pragma unroll
            for (int s = 0; s < NCOLS; s++) {
                float m = v[s][0];
                #pragma unroll
                for (int j = 1; j < NS; j++) m = fmaxf(m, v[s][j]);
                float inv = __fdividef(1.0f, m);
                #pragma unroll
                for (int j = 0; j < NS; j++) v[s][j] *= inv;
                csc[s] += __logf(m);
            }
        }
    }
    #pragma unroll
    for (int s = 0; s < NCOLS; s++) {   // final normalize (max -> 1)
        float m = v[s][0];
        #pragma unroll
        for (int j = 1; j < NS; j++) m = fmaxf(m, v[s][j]);
        float inv = __fdividef(1.0f, m);
        #pragma unroll
        for (int j = 0; j < NS; j++) v[s][j] *= inv;
        csc[s] += __logf(m);
    }
}

__global__ void __launch_bounds__(128) chunk_kernel(
    const float* __restrict__ feats, const float* __restrict__ trans,
    const int* __restrict__ tags, const int* __restrict__ lengths,
    int B, int T, int C)
{
    __shared__ float s_tr[KK * KK];
    if (threadIdx.x < KK * KK) s_tr[threadIdx.x] = trans[threadIdx.x];
    __syncthreads();

    int u = blockIdx.x * blockDim.x + threadIdx.x;
    if (u >= NCH * B) return;
    int c = u / B;
    int slot = u - c * B;
    int b = g_perm[slot];
    int L = lengths[b];
    int t0 = c * C;
    if (t0 >= L) return;              // empty chunk (only possible for c>0)
    int t1 = min(L, t0 + C);

    const float* fb  = feats + (size_t)b * T * KK;
    const int*   tgb = tags  + (size_t)b * T;

    float et[NS][NS];
    #pragma unroll
    for (int j = 0; j < NS; j++)
        #pragma unroll
        for (int i = 0; i < NS; i++) et[j][i] = __expf(s_tr[j * KK + i]);

    float gold = 0.f;
    int prev;

    if (c == 0) {
        // closed-form first step: alpha1[j] = trans[j,START] + feat[0,j]
        float f[NS];
        #pragma unroll
        for (int j = 0; j < NS; j++) f[j] = __ldg(&fb[j]);
        float a[NS];
        #pragma unroll
        for (int j = 0; j < NS; j++) a[j] = s_tr[j * KK + 7] + f[j];
        float m = a[0];
        #pragma unroll
        for (int j = 1; j < NS; j++) m = fmaxf(m, a[j]);
        float v[1][NS]; float csc[1];
        #pragma unroll
        for (int j = 0; j < NS; j++) v[0][j] = __expf(a[j] - m);
        csc[0] = m;

        int tag = __ldg(&tgb[0]);
        float fe = f[0];
        #pragma unroll
        for (int j = 1; j < NS; j++) fe = (tag == j) ? f[j] : fe;
        gold = s_tr[tag * KK + 7] + fe;
        prev = tag;

        run_steps<1>(1, t1, fb, tgb, s_tr, et, v, csc, gold, prev);

        #pragma unroll
        for (int j = 0; j < NS; j++)
            g_scratch[(size_t)(c * 64 + j) * B + b] = v[0][j];
        g_scratch[(size_t)(c * 64 + 7) * B + b] = csc[0];
    } else {
        float v[NS][NS]; float csc[NS];
        #pragma unroll
        for (int s = 0; s < NS; s++) {
            #pragma unroll
            for (int j = 0; j < NS; j++) v[s][j] = (s == j) ? 1.f : 0.f;
            csc[s] = 0.f;
        }
        prev = __ldg(&tgb[t0 - 1]);

        run_steps<NS>(t0, t1, fb, tgb, s_tr, et, v, csc, gold, prev);

        #pragma unroll
        for (int s = 0; s < NS; s++) {
            #pragma unroll
            for (int j = 0; j < NS; j++)
                g_scratch[(size_t)(c * 64 + s * 8 + j) * B + b] = v[s][j];
            g_scratch[(size_t)(c * 64 + s * 8 + 7) * B + b] = csc[s];
        }
    }
    g_gold[c * B + b] = gold;
}

// ---------------------------------------------------------------------------
// Fold chunk operators per sentence (coalesced over original b), finish
// forward score, gold score, write per-sentence (fwd - gold).
// ---------------------------------------------------------------------------
__global__ void combine_kernel(
    const float* __restrict__ trans, const int* __restrict__ tags,
    const int* __restrict__ lengths, int B, int T, int C)
{
    int b = blockIdx.x * blockDim.x + threadIdx.x;
    if (b >= B) return;
    int L = lengths[b];

    float v[NS];
    #pragma unroll
    for (int j = 0; j < NS; j++) v[j] = g_scratch[(size_t)j * B + b];
    float sc = g_scratch[(size_t)7 * B + b];
    float gold = g_gold[b];

    for (int c = 1; c < NCH && c * C < L; c++) {
        gold += g_gold[c * B + b];
        float cs[NS];
        #pragma unroll
        for (int s = 0; s < NS; s++)
            cs[s] = g_scratch[(size_t)(c * 64 + s * 8 + 7) * B + b];
        float csmax = cs[0];
        #pragma unroll
        for (int s = 1; s < NS; s++) csmax = fmaxf(csmax, cs[s]);
        float w[NS];
        #pragma unroll
        for (int s = 0; s < NS; s++) w[s] = v[s] * __expf(cs[s] - csmax);

        float nv[NS];
        #pragma unroll
        for (int j = 0; j < NS; j++) nv[j] = 0.f;
        #pragma unroll
        for (int s = 0; s < NS; s++) {
            #pragma unroll
            for (int j = 0; j < NS; j++)
                nv[j] = fmaf(g_scratch[(size_t)(c * 64 + s * 8 + j) * B + b],
                             w[s], nv[j]);
        }
        float m = nv[0];
        #pragma unroll
        for (int j = 1; j < NS; j++) m = fmaxf(m, nv[j]);
        float inv = __fdividef(1.f, m);
        #pragma unroll
        for (int j = 0; j < NS; j++) v[j] = nv[j] * inv;
        sc += csmax + __logf(m);
    }

    float acc = 0.f;
    #pragma unroll
    for (int i = 0; i < NS; i++)
        acc += v[i] * __expf(__ldg(&trans[8 * KK + i]));
    float fwd = sc + __logf(acc);

    int last = __ldg(&tags[(size_t)b * T + (L - 1)]);
    gold += __ldg(&trans[8 * KK + last]);

    g_psent[b] = fwd - gold;
}

__global__ void reduce_kernel(float* __restrict__ out, int B)
{
    __shared__ float s[256];
    int tid = threadIdx.x;
    float a = 0.f;
    for (int i = tid; i < B; i += 256) a += g_psent[i];
    s[tid] = a;
    __syncthreads();
    for (int st = 128; st > 0; st >>= 1) {
        if (tid < st) s[tid] += s[tid + st];
        __syncthreads();
    }
    if (tid == 0) out[0] = s[0] / (float)B;
}

extern "C" void kernel_launch(void* const* d_in, const int* in_sizes, int n_in,
                              void* d_out, int out_size)
{
    const float* feats   = (const float*)d_in[0];
    const float* trans   = (const float*)d_in[1];
    const int*   tags    = (const int*)d_in[2];
    const int*   lengths = (const int*)d_in[3];

    int B = in_sizes[3];
    int T = in_sizes[2] / B;
    int C = (T + NCH - 1) / NCH;

    perm_kernel<<<1, 1024>>>(lengths, B, C);
    int total = NCH * B;
    chunk_kernel<<<(total + 127) / 128, 128>>>(feats, trans, tags, lengths, B, T, C);
    combine_kernel<<<(B + 127) / 128, 128>>>(trans, tags, lengths, B, T, C);
    reduce_kernel<<<1, 256>>>((float*)d_out, B);
}

// round 2
// speedup vs baseline: 1.5510x; 1.5510x over previous
#include <cuda_runtime.h>
#include <cuda_bf16.h>

// CRF NLL, B x T x K=9 (START=7, STOP=8), 7 live states.
// Parallel time-chunk scan in linear domain with periodic rescaling.
// 8-lane groups: lanes 0..6 evolve one operator column each, lane 7 does gold.

#define NCH 32
#define NS  7
#define KK  9
#define MAXB 2048

__device__ float g_scratch[(size_t)NCH * MAXB * 64]; // [(c*B+b)*64 + s*8 + j]
__device__ float g_gold[NCH * MAXB];
__device__ int   g_perm[MAXB];
__device__ float g_psent[MAXB];

// ---------------------------------------------------------------------------
__global__ void perm_kernel(const int* __restrict__ lengths, int B, int C)
{
    __shared__ int hist[NCH];
    __shared__ int off[NCH];
    int tid = threadIdx.x;
    if (tid < NCH) hist[tid] = 0;
    __syncthreads();
    for (int b = tid; b < B; b += blockDim.x) {
        int bk = (lengths[b] - 1) / C;
        if (bk > NCH - 1) bk = NCH - 1;
        atomicAdd(&hist[bk], 1);
    }
    __syncthreads();
    if (tid == 0) {
        int acc = 0;
        for (int i = 0; i < NCH; i++) { off[i] = acc; acc += hist[i]; }
    }
    __syncthreads();
    for (int b = tid; b < B; b += blockDim.x) {
        int bk = (lengths[b] - 1) / C;
        if (bk > NCH - 1) bk = NCH - 1;
        int pos = atomicAdd(&off[bk], 1);
        g_perm[pos] = b;
    }
}

// ---------------------------------------------------------------------------
__global__ void __launch_bounds__(256) chunk_kernel(
    const float* __restrict__ feats, const float* __restrict__ trans,
    const int* __restrict__ tags, const int* __restrict__ lengths,
    int B, int T, int C)
{
    __shared__ float s_tr[KK * KK];
    __shared__ float s_et[NS * NS];
    int tid = threadIdx.x;
    if (tid < KK * KK) s_tr[tid] = trans[tid];
    __syncthreads();
    if (tid < NS * NS) s_et[tid] = __expf(s_tr[(tid / NS) * KK + (tid % NS)]);
    __syncthreads();

    int g = (blockIdx.x * blockDim.x + tid) >> 3;
    if (g >= NCH * B) return;
    int lane = tid & 7;
    unsigned grpw  = (unsigned)(tid & 31) & 24u;
    unsigned mask8 = 0xFFu << grpw;

    int c = g / B;
    int slot = g - c * B;
    int b = g_perm[slot];
    int L = lengths[b];
    int t0 = c * C;
    if (t0 >= L) return;               // whole 8-lane group exits together
    int t1 = min(L, t0 + C);

    const float* fb  = feats + (size_t)b * T * KK;
    const int*   tgb = tags  + (size_t)b * T;
    size_t base = ((size_t)c * B + b) * 64;

    float gold = 0.f;
    int prev = 0;

    if (c == 0) {
        // -------- vector path: lane j holds alpha[j] --------
        float etrow[NS];
        int jr = (lane < NS) ? lane : 0;
        #pragma unroll
        for (int i = 0; i < NS; i++) etrow[i] = s_et[jr * NS + i];

        // first step (t=0): alpha[j] = trans[j,START] + feat[0,j]
        float fv = 0.f; int tg = 0;
        if (lane < NS) fv = __ldg(&fb[lane]);
        else           tg = __ldg(&tgb[0]);
        float x = (lane < NS) ? (s_tr[lane * KK + 7] + fv) : -1e30f;
        float m = x;
        #pragma unroll
        for (int d = 1; d < 8; d <<= 1) m = fmaxf(m, __shfl_xor_sync(mask8, m, d));
        float a = (lane < NS) ? __expf(x - m) : 0.f;
        float csc = m;
        float ftg = __shfl_sync(mask8, fv, grpw + (unsigned)tg);
        if (lane == 7) { gold = s_tr[tg * KK + 7] + ftg; prev = tg; }

        int rc = 0;
        for (int t = 1; t < t1; ++t) {
            float f2 = 0.f; int tg2 = 0;
            if (lane < NS) f2 = __ldg(&fb[t * KK + lane]);
            else           tg2 = __ldg(&tgb[t]);
            float efl = __expf(f2);
            float a0 = __shfl_sync(mask8, a, grpw + 0);
            float a1 = __shfl_sync(mask8, a, grpw + 1);
            float a2 = __shfl_sync(mask8, a, grpw + 2);
            float a3 = __shfl_sync(mask8, a, grpw + 3);
            float a4 = __shfl_sync(mask8, a, grpw + 4);
            float a5 = __shfl_sync(mask8, a, grpw + 5);
            float a6 = __shfl_sync(mask8, a, grpw + 6);
            float nv = etrow[0] * a0;
            nv = fmaf(etrow[1], a1, nv);
            nv = fmaf(etrow[2], a2, nv);
            nv = fmaf(etrow[3], a3, nv);
            nv = fmaf(etrow[4], a4, nv);
            nv = fmaf(etrow[5], a5, nv);
            nv = fmaf(etrow[6], a6, nv);
            if (lane < NS) a = nv * efl;
            float ft2 = __shfl_sync(mask8, f2, grpw + (unsigned)tg2);
            if (lane == 7) { gold += s_tr[tg2 * KK + prev] + ft2; prev = tg2; }
            if (++rc == 4) {
                rc = 0;
                float mm = a;
                #pragma unroll
                for (int d = 1; d < 8; d <<= 1)
                    mm = fmaxf(mm, __shfl_xor_sync(mask8, mm, d));
                mm = fmaxf(mm, 1e-30f);
                float inv = __fdividef(1.f, mm);
                if (lane < NS) a *= inv;
                csc += __logf(mm);
            }
        }
        float mm = a;
        #pragma unroll
        for (int d = 1; d < 8; d <<= 1)
            mm = fmaxf(mm, __shfl_xor_sync(mask8, mm, d));
        mm = fmaxf(mm, 1e-30f);
        float inv = __fdividef(1.f, mm);
        if (lane < NS) a *= inv;
        csc += __logf(mm);

        if (lane < NS) g_scratch[base + lane] = a;
        if (lane == 7) {
            g_scratch[base + 7] = csc;
            g_gold[c * B + b] = gold;
        }
    } else {
        // -------- matrix path: lane s evolves operator column s --------
        float et[NS][NS];
        #pragma unroll
        for (int j = 0; j < NS; j++)
            #pragma unroll
            for (int i = 0; i < NS; i++) et[j][i] = s_et[j * NS + i];

        float v[NS];
        #pragma unroll
        for (int j = 0; j < NS; j++) v[j] = (j == lane) ? 1.f : 0.f; // lane7: 0s
        float csc = 0.f;
        if (lane == 7) prev = __ldg(&tgb[t0 - 1]);

        int rc = 0;
        for (int t = t0; t < t1; ++t) {
            float fv = 0.f; int tg = 0;
            if (lane < NS) fv = __ldg(&fb[t * KK + lane]);
            else           tg = __ldg(&tgb[t]);
            float efl = __expf(fv);
            float e0 = __shfl_sync(mask8, efl, grpw + 0);
            float e1 = __shfl_sync(mask8, efl, grpw + 1);
            float e2 = __shfl_sync(mask8, efl, grpw + 2);
            float e3 = __shfl_sync(mask8, efl, grpw + 3);
            float e4 = __shfl_sync(mask8, efl, grpw + 4);
            float e5 = __shfl_sync(mask8, efl, grpw + 5);
            float e6 = __shfl_sync(mask8, efl, grpw + 6);
            float ftg = __shfl_sync(mask8, fv, grpw + (unsigned)tg);
            if (lane == 7) { gold += s_tr[tg * KK + prev] + ftg; prev = tg; }

            float nv[NS];
            #pragma unroll
            for (int j = 0; j < NS; j++) {
                float acc = et[j][0] * v[0];
                #pragma unroll
                for (int i = 1; i < NS; i++) acc = fmaf(et[j][i], v[i], acc);
                nv[j] = acc;
            }
            v[0] = nv[0] * e0; v[1] = nv[1] * e1; v[2] = nv[2] * e2;
            v[3] = nv[3] * e3; v[4] = nv[4] * e4; v[5] = nv[5] * e5;
            v[6] = nv[6] * e6;

            if (++rc == 4) {
                rc = 0;
                float mm = v[0];
                #pragma unroll
                for (int j = 1; j < NS; j++) mm = fmaxf(mm, v[j]);
                mm = fmaxf(mm, 1e-30f);
                float inv = __fdividef(1.f, mm);
                #pragma unroll
                for (int j = 0; j < NS; j++) v[j] *= inv;
                csc += __logf(mm);
            }
        }
        float mm = v[0];
        #pragma unroll
        for (int j = 1; j < NS; j++) mm = fmaxf(mm, v[j]);
        mm = fmaxf(mm, 1e-30f);
        float inv = __fdividef(1.f, mm);
        #pragma unroll
        for (int j = 0; j < NS; j++) v[j] *= inv;
        csc += __logf(mm);

        if (lane < NS) {
            #pragma unroll
            for (int j = 0; j < NS; j++)
                g_scratch[base + lane * 8 + j] = v[j];
            g_scratch[base + lane * 8 + 7] = csc;
        } else {
            g_gold[c * B + b] = gold;
        }
    }
}

// ---------------------------------------------------------------------------
// 8 lanes per sentence: lane j holds alpha[j], fold chunk operators.
// ---------------------------------------------------------------------------
__global__ void __launch_bounds__(256) combine_kernel(
    const float* __restrict__ trans, const int* __restrict__ tags,
    const int* __restrict__ lengths, int B, int T, int C)
{
    int tid = threadIdx.x;
    int g = (blockIdx.x * blockDim.x + tid) >> 3;
    if (g >= B) return;
    int lane = tid & 7;
    unsigned grpw  = (unsigned)(tid & 31) & 24u;
    unsigned mask8 = 0xFFu << grpw;
    int b = g_perm[g];
    int L = lengths[b];

    float v  = (lane < NS) ? g_scratch[(size_t)b * 64 + lane] : 0.f;
    float sc = g_scratch[(size_t)b * 64 + 7];
    float gold = (lane == 7) ? g_gold[b] : 0.f;

    for (int c = 1; c < NCH && c * C < L; ++c) {
        size_t base = ((size_t)c * B + b) * 64;
        float cs = (lane < NS) ? g_scratch[base + lane * 8 + 7] : -1e30f;
        float csmax = cs;
        #pragma unroll
        for (int d = 1; d < 8; d <<= 1)
            csmax = fmaxf(csmax, __shfl_xor_sync(mask8, csmax, d));
        float w = (lane < NS) ? v * __expf(cs - csmax) : 0.f;
        float nv = 0.f;
        #pragma unroll
        for (int s = 0; s < NS; ++s) {
            float ws = __shfl_sync(mask8, w, grpw + (unsigned)s);
            float M = g_scratch[base + s * 8 + lane]; // lane7 reads csc slot: unused
            nv = fmaf(M, ws, nv);
        }
        if (lane == 7) nv = 0.f;
        float mm = nv;
        #pragma unroll
        for (int d = 1; d < 8; d <<= 1)
            mm = fmaxf(mm, __shfl_xor_sync(mask8, mm, d));
        mm = fmaxf(mm, 1e-30f);
        v = nv * __fdividef(1.f, mm);
        sc += csmax + __logf(mm);
        if (lane == 7) gold += g_gold[c * B + b];
    }

    float term = (lane < NS) ? v * __expf(__ldg(&trans[8 * KK + lane])) : 0.f;
    #pragma unroll
    for (int d = 1; d < 8; d <<= 1)
        term += __shfl_xor_sync(mask8, term, d);
    float fwd = sc + __logf(term);
    if (lane == 7) {
        int last = __ldg(&tags[(size_t)b * T + (L - 1)]);
        gold += __ldg(&trans[8 * KK + last]);
        g_psent[b] = fwd - gold;
    }
}

// ---------------------------------------------------------------------------
__global__ void reduce_kernel(float* __restrict__ out, int B)
{
    __shared__ float s[256];
    int tid = threadIdx.x;
    float a = 0.f;
    for (int i = tid; i < B; i += 256) a += g_psent[i];
    s[tid] = a;
    __syncthreads();
    for (int st = 128; st > 0; st >>= 1) {
        if (tid < st) s[tid] += s[tid + st];
        __syncthreads();
    }
    if (tid == 0) out[0] = s[0] / (float)B;
}

extern "C" void kernel_launch(void* const* d_in, const int* in_sizes, int n_in,
                              void* d_out, int out_size)
{
    const float* feats   = (const float*)d_in[0];
    const float* trans   = (const float*)d_in[1];
    const int*   tags    = (const int*)d_in[2];
    const int*   lengths = (const int*)d_in[3];

    int B = in_sizes[3];
    int T = in_sizes[2] / B;
    int C = (T + NCH - 1) / NCH;

    perm_kernel<<<1, 1024>>>(lengths, B, C);
    int thr = NCH * B * 8;
    chunk_kernel<<<(thr + 255) / 256, 256>>>(feats, trans, tags, lengths, B, T, C);
    combine_kernel<<<(B * 8 + 255) / 256, 256>>>(trans, tags, lengths, B, T, C);
    reduce_kernel<<<1, 256>>>((float*)d_out, B);
}